// round 12
// baseline (speedup 1.0000x reference)
#include <cuda_runtime.h>
#include <cuda_bf16.h>
#include <cstdint>

// SPLoPAdapter as ONE GEMM with pre-packed operands:
//   prep kernel:  As2[ij][kw]  = bf16x2(pos[2kw, ij], pos[2kw+1, ij])   (4096x32 u32)
//                 G2 [ab][kw]  = bf16x2(w[2kw,a]*h[2kw,b], w[2kw+1,a]*h[2kw+1,b]) (1024x32 u32)
//   gemm kernel:  delta2[ij,ab] = sum_k pos * G ; out = weights + scatter(delta2)
// GEMM CTA: 256 thr, tile 128(ij) x 64(ab); cp.async operand copy (no ALU prep),
// one barrier, mma, per-warp transpose epilogue (no post-MMA CTA barrier).

__device__ uint32_t g_As2[4096 * 32];   // 512 KB scratch
__device__ uint32_t g_G2[1024 * 32];    // 128 KB scratch

static constexpr int ASW = 36;   // smem row stride in u32 words (conflict-free)
static constexpr int BSW = 36;
static constexpr int TBS = 36;   // per-warp transpose buffer stride (floats)

static constexpr int OFF_AS = 0;
static constexpr int OFF_BT = OFF_AS + 128 * ASW * 4;          // 18432
static constexpr int OFF_TB = OFF_BT + 64 * BSW * 4;           // 27648
static constexpr int SMEM_BYTES = OFF_TB + 8 * 32 * TBS * 4;   // 64512

__device__ __forceinline__ void mma_bf16(float* d, const uint32_t* a, const uint32_t* b) {
    asm volatile(
        "mma.sync.aligned.m16n8k16.row.col.f32.bf16.bf16.f32 "
        "{%0,%1,%2,%3}, {%4,%5,%6,%7}, {%8,%9}, {%0,%1,%2,%3};"
        : "+f"(d[0]), "+f"(d[1]), "+f"(d[2]), "+f"(d[3])
        : "r"(a[0]), "r"(a[1]), "r"(a[2]), "r"(a[3]), "r"(b[0]), "r"(b[1]));
}

__device__ __forceinline__ uint32_t packbf(float f0, float f1) {
    __nv_bfloat162 p = __floats2bfloat162_rn(f0, f1);  // low=f0(k even), high=f1(k odd)
    return *(uint32_t*)&p;
}

__device__ __forceinline__ uint32_t smem_u32(const void* p) {
    uint32_t a;
    asm("{ .reg .u64 t; cvta.to.shared.u64 t, %1; cvt.u32.u64 %0, t; }" : "=r"(a) : "l"(p));
    return a;
}
#define CP_ASYNC16(dst, src) \
    asm volatile("cp.async.cg.shared.global [%0], [%1], 16;" :: "r"(dst), "l"(src))
#define CP_COMMIT() asm volatile("cp.async.commit_group;" ::: "memory")
#define CP_WAIT0()  asm volatile("cp.async.wait_group 0;" ::: "memory")

// ---------------- prep kernel ----------------
__global__ void __launch_bounds__(256) splopa_prep_kernel(
    const float* __restrict__ pos,
    const float* __restrict__ pw,
    const float* __restrict__ ph)
{
    const int tid = threadIdx.x;

    if (blockIdx.x < 16) {
        // As2: transpose-pack pos. thread = one ij; lane-consecutive ij => coalesced LDG.
        const int ij = blockIdx.x * 256 + tid;
        const float* pp = pos + ij;
        uint32_t buf[32];
        #pragma unroll
        for (int kw = 0; kw < 32; kw++)
            buf[kw] = packbf(pp[(size_t)(2 * kw) * 4096], pp[(size_t)(2 * kw + 1) * 4096]);
        uint4* dst = (uint4*)&g_As2[ij * 32];
        #pragma unroll
        for (int c = 0; c < 8; c++)
            dst[c] = ((const uint4*)buf)[c];
    } else {
        // G2: 1024 ab rows, 4 per thread.
        #pragma unroll
        for (int r = 0; r < 4; r++) {
            const int ab = tid + r * 256;
            const int a = ab >> 5, b = ab & 31;
            uint32_t buf[32];
            #pragma unroll
            for (int kw = 0; kw < 32; kw++) {
                const float f0 = pw[(2 * kw) * 32 + a]     * ph[(2 * kw) * 32 + b];
                const float f1 = pw[(2 * kw + 1) * 32 + a] * ph[(2 * kw + 1) * 32 + b];
                buf[kw] = packbf(f0, f1);
            }
            uint4* dst = (uint4*)&g_G2[ab * 32];
            #pragma unroll
            for (int c = 0; c < 8; c++)
                dst[c] = ((const uint4*)buf)[c];
        }
    }
}

// ---------------- GEMM kernel ----------------
__global__ void __launch_bounds__(256, 3) splopa_mma_kernel(
    const float* __restrict__ weights,
    float* __restrict__ out)
{
    __shared__ __align__(16) char smem[SMEM_BYTES];
    uint32_t* As32 = (uint32_t*)(smem + OFF_AS);
    uint32_t* Bt32 = (uint32_t*)(smem + OFF_BT);

    const int tid  = threadIdx.x;
    const int wid  = tid >> 5;
    const int lane = tid & 31;
    const int g    = lane >> 2;
    const int tig  = lane & 3;

    const int bx = blockIdx.x;          // ab block: a in {2bx, 2bx+1} -> G2 rows 64bx..+63
    const int by = blockIdx.y;          // ij block: rows 128by..+127
    const int ij0 = by * 128;
    const int ab0 = bx * 64;

    // ---- single staging phase: 1536 cp.async 16B chunks ----
    {
        const uint32_t as_base = smem_u32(As32);
        const uint32_t bt_base = smem_u32(Bt32);
        // As: 128 rows x 8 chunks = 1024 chunks (4 per thread)
        #pragma unroll
        for (int it = 0; it < 4; it++) {
            const int q   = tid + it * 256;
            const int row = q >> 3;
            const int c   = q & 7;
            CP_ASYNC16(as_base + (row * ASW + c * 4) * 4,
                       (const char*)&g_As2[(ij0 + row) * 32] + c * 16);
        }
        // Bt: 64 rows x 8 chunks = 512 chunks (2 per thread)
        #pragma unroll
        for (int it = 0; it < 2; it++) {
            const int q   = tid + it * 256;
            const int row = q >> 3;
            const int c   = q & 7;
            CP_ASYNC16(bt_base + (row * BSW + c * 4) * 4,
                       (const char*)&g_G2[(ab0 + row) * 32] + c * 16);
        }
        CP_COMMIT();
        CP_WAIT0();
    }
    __syncthreads();     // only CTA-wide barrier

    // ---- main GEMM: warp tile 32(ij) x 32(ab) ----
    const int mw = wid >> 1;            // i_loc = mw>>1, j-window = (mw&1)*32
    const int nw = wid & 1;             // a offset
    const int rbase = mw * 32;
    const int cbase = nw * 32;

    float d[8][4];
    #pragma unroll
    for (int x = 0; x < 8; x++)
        #pragma unroll
        for (int c = 0; c < 4; c++)
            d[x][c] = 0.0f;

    #pragma unroll
    for (int kt = 0; kt < 4; kt++) {
        const int kw0 = kt * 8 + tig;

        uint32_t a[2][4];
        #pragma unroll
        for (int mt = 0; mt < 2; mt++) {
            const int r0 = rbase + mt * 16 + g;
            a[mt][0] = As32[r0 * ASW + kw0];
            a[mt][1] = As32[(r0 + 8) * ASW + kw0];
            a[mt][2] = As32[r0 * ASW + kw0 + 4];
            a[mt][3] = As32[(r0 + 8) * ASW + kw0 + 4];
        }

        uint32_t b[4][2];
        #pragma unroll
        for (int nt = 0; nt < 4; nt++) {
            const int col = cbase + nt * 8 + g;
            b[nt][0] = Bt32[col * BSW + kw0];
            b[nt][1] = Bt32[col * BSW + kw0 + 4];
        }

        #pragma unroll
        for (int mt = 0; mt < 2; mt++)
            #pragma unroll
            for (int nt = 0; nt < 4; nt++)
                mma_bf16(d[mt * 4 + nt], a[mt], b[nt]);
    }

    // ---- per-warp transpose: frag tile (32 j x 32 b) -> tb ----
    float* tb = (float*)(smem + OFF_TB) + wid * 32 * TBS;

    #pragma unroll
    for (int mt = 0; mt < 2; mt++) {
        #pragma unroll
        for (int nt = 0; nt < 4; nt++) {
            const int bb = nt * 8 + 2 * tig;
            const float* dd = d[mt * 4 + nt];
            *(float2*)&tb[(mt * 16 + g) * TBS + bb]     = make_float2(dd[0], dd[1]);
            *(float2*)&tb[(mt * 16 + g + 8) * TBS + bb] = make_float2(dd[2], dd[3]);
        }
    }
    __syncwarp();

    // ---- per-warp coalesced stream: 1024 contiguous floats of one row ----
    const int row_g   = (by * 2 + (mw >> 1)) * 32 + bx * 2 + nw;
    const int colbase = (mw & 1) * 1024;
    const float* wseg = weights + (size_t)row_g * 2048 + colbase;
    float*       oseg = out     + (size_t)row_g * 2048 + colbase;

    #pragma unroll
    for (int it = 0; it < 8; it++) {
        const int j  = it * 4 + (lane >> 3);
        const int c4 = (lane & 7) * 4;

        const float4 dv = *(const float4*)&tb[j * TBS + c4];
        const int col = j * 32 + c4;
        const float4 wv = *(const float4*)(wseg + col);
        float4 ov;
        ov.x = wv.x + dv.x;
        ov.y = wv.y + dv.y;
        ov.z = wv.z + dv.z;
        ov.w = wv.w + dv.w;
        *(float4*)(oseg + col) = ov;
    }
}

extern "C" void kernel_launch(void* const* d_in, const int* in_sizes, int n_in,
                              void* d_out, int out_size)
{
    const float* weights = (const float*)d_in[0];
    const float* pos     = (const float*)d_in[1];
    const float* pw      = (const float*)d_in[2];
    const float* ph      = (const float*)d_in[3];
    float* out           = (float*)d_out;

    splopa_prep_kernel<<<17, 256>>>(pos, pw, ph);
    dim3 grid(16, 32);
    splopa_mma_kernel<<<grid, dim3(256)>>>(weights, out);
}

// round 14
// speedup vs baseline: 2.0902x; 2.0902x over previous
#include <cuda_runtime.h>
#include <cuda_bf16.h>
#include <cstdint>

// SPLoPAdapter as ONE GEMM with pre-packed operands (parallel prep):
//   prep:  As2[ij][kw] = bf16x2(pos[2kw,ij], pos[2kw+1,ij])               (4096x32 u32)
//          G2 [ab][kw] = bf16x2(w[2kw,a]*h[2kw,b], w[2kw+1,a]*h[2kw+1,b]) (1024x32 u32)
//   gemm:  delta2 = pos @ G ; out = weights + scatter(delta2)
// GEMM: cp.async group A = operands, group B = per-warp weights (32KB, correct size);
// 4-pass per-warp transpose (8-row tb); no CTA barrier after MMA.

__device__ uint32_t g_As2[4096 * 32];   // 512 KB scratch
__device__ uint32_t g_G2[1024 * 32];    // 128 KB scratch

static constexpr int ASW = 36;
static constexpr int BSW = 36;
static constexpr int TBS = 36;

static constexpr int OFF_AS = 0;                          // 128*36*4 = 18432
static constexpr int OFF_BT = 18432;                      // 64*36*4  =  9216
static constexpr int OFF_TB = 27648;                      // 8 warps * 8 rows * 36 * 4 = 9216
static constexpr int OFF_WT = 36864;                      // 4 rows * 2048 * 4 = 32768
static constexpr int SMEM_BYTES = 69632;                  // 3 CTAs/SM

__device__ __forceinline__ void mma_bf16(float* d, const uint32_t* a, const uint32_t* b) {
    asm volatile(
        "mma.sync.aligned.m16n8k16.row.col.f32.bf16.bf16.f32 "
        "{%0,%1,%2,%3}, {%4,%5,%6,%7}, {%8,%9}, {%0,%1,%2,%3};"
        : "+f"(d[0]), "+f"(d[1]), "+f"(d[2]), "+f"(d[3])
        : "r"(a[0]), "r"(a[1]), "r"(a[2]), "r"(a[3]), "r"(b[0]), "r"(b[1]));
}

__device__ __forceinline__ uint32_t packbf(float f0, float f1) {
    __nv_bfloat162 p = __floats2bfloat162_rn(f0, f1);  // low = even k, high = odd k
    return *(uint32_t*)&p;
}

__device__ __forceinline__ uint32_t smem_u32(const void* p) {
    uint32_t a;
    asm("{ .reg .u64 t; cvta.to.shared.u64 t, %1; cvt.u32.u64 %0, t; }" : "=r"(a) : "l"(p));
    return a;
}
#define CP_ASYNC16(dst, src) \
    asm volatile("cp.async.cg.shared.global [%0], [%1], 16;" :: "r"(dst), "l"(src))
#define CP_COMMIT() asm volatile("cp.async.commit_group;" ::: "memory")
#define CP_WAIT(n)  asm volatile("cp.async.wait_group %0;" :: "n"(n) : "memory")

// ---------------- prep kernel: one thread per 16B output chunk ----------------
__global__ void __launch_bounds__(256) splopa_prep_kernel(
    const float* __restrict__ pos,
    const float* __restrict__ pw,
    const float* __restrict__ ph)
{
    const int t = blockIdx.x * 256 + threadIdx.x;

    if (blockIdx.x < 128) {
        // As2: t in [0, 32768): ij = t>>3, quad q = t&7
        const int ij = t >> 3;
        const int q  = t & 7;
        uint32_t pk[4];
        #pragma unroll
        for (int e = 0; e < 4; e++) {
            const int k = 8 * q + 2 * e;
            pk[e] = packbf(pos[(size_t)k * 4096 + ij], pos[(size_t)(k + 1) * 4096 + ij]);
        }
        *(uint4*)&g_As2[ij * 32 + 4 * q] = make_uint4(pk[0], pk[1], pk[2], pk[3]);
    } else {
        // G2: t2 in [0, 8192): ab = t2>>3, quad q = t2&7
        const int t2 = t - 128 * 256;
        const int ab = t2 >> 3;
        const int q  = t2 & 7;
        const int a = ab >> 5, b = ab & 31;
        uint32_t pk[4];
        #pragma unroll
        for (int e = 0; e < 4; e++) {
            const int k = 8 * q + 2 * e;
            const float f0 = pw[k * 32 + a]       * ph[k * 32 + b];
            const float f1 = pw[(k + 1) * 32 + a] * ph[(k + 1) * 32 + b];
            pk[e] = packbf(f0, f1);
        }
        *(uint4*)&g_G2[ab * 32 + 4 * q] = make_uint4(pk[0], pk[1], pk[2], pk[3]);
    }
}

// ---------------- GEMM kernel ----------------
__global__ void __launch_bounds__(256, 3) splopa_mma_kernel(
    const float* __restrict__ weights,
    float* __restrict__ out)
{
    __shared__ __align__(16) char smem[SMEM_BYTES];
    uint32_t* As32 = (uint32_t*)(smem + OFF_AS);
    uint32_t* Bt32 = (uint32_t*)(smem + OFF_BT);

    const int tid  = threadIdx.x;
    const int wid  = tid >> 5;
    const int lane = tid & 31;
    const int g    = lane >> 2;
    const int tig  = lane & 3;

    const int bx = blockIdx.x;          // a in {2bx, 2bx+1}
    const int by = blockIdx.y;          // ij rows 128by..+127
    const int ij0 = by * 128;
    const int ab0 = bx * 64;

    const int mw = wid >> 1;            // i_loc = mw>>1, j-window = (mw&1)*32
    const int nw = wid & 1;             // a offset
    const int row_g   = (by * 2 + (mw >> 1)) * 32 + bx * 2 + nw;
    const int colbase = (mw & 1) * 1024;

    // ---- group A: operands As + Bt (6 chunks/thread) ----
    {
        const uint32_t as_base = smem_u32(As32);
        const uint32_t bt_base = smem_u32(Bt32);
        #pragma unroll
        for (int it = 0; it < 4; it++) {
            const int q   = tid + it * 256;
            const int row = q >> 3;
            const int c   = q & 7;
            CP_ASYNC16(as_base + (row * ASW + c * 4) * 4,
                       (const char*)&g_As2[(ij0 + row) * 32] + c * 16);
        }
        #pragma unroll
        for (int it = 0; it < 2; it++) {
            const int q   = tid + it * 256;
            const int row = q >> 3;
            const int c   = q & 7;
            CP_ASYNC16(bt_base + (row * BSW + c * 4) * 4,
                       (const char*)&g_G2[(ab0 + row) * 32] + c * 16);
        }
        CP_COMMIT();
    }
    // ---- group B: this warp's own 4KB weights segment (8 chunks/lane) ----
    {
        const uint32_t wt_base = smem_u32(smem + OFF_WT) + (uint32_t)wid * 4096;
        const float* wseg = weights + (size_t)row_g * 2048 + colbase;
        #pragma unroll
        for (int c = 0; c < 8; c++) {
            const int f4 = lane + c * 32;          // float4 slot 0..255
            CP_ASYNC16(wt_base + f4 * 16, wseg + f4 * 4);
        }
        CP_COMMIT();
    }

    CP_WAIT(1);          // group A complete; weights still in flight
    __syncthreads();     // only CTA-wide barrier

    // ---- main GEMM: warp tile 32(ij) x 32(ab) ----
    const int rbase = mw * 32;
    const int cbase = nw * 32;

    float d[8][4];
    #pragma unroll
    for (int x = 0; x < 8; x++)
        #pragma unroll
        for (int c = 0; c < 4; c++)
            d[x][c] = 0.0f;

    #pragma unroll
    for (int kt = 0; kt < 4; kt++) {
        const int kw0 = kt * 8 + tig;

        uint32_t a[2][4];
        #pragma unroll
        for (int mt = 0; mt < 2; mt++) {
            const int r0 = rbase + mt * 16 + g;
            a[mt][0] = As32[r0 * ASW + kw0];
            a[mt][1] = As32[(r0 + 8) * ASW + kw0];
            a[mt][2] = As32[r0 * ASW + kw0 + 4];
            a[mt][3] = As32[(r0 + 8) * ASW + kw0 + 4];
        }

        uint32_t b[4][2];
        #pragma unroll
        for (int nt = 0; nt < 4; nt++) {
            const int col = cbase + nt * 8 + g;
            b[nt][0] = Bt32[col * BSW + kw0];
            b[nt][1] = Bt32[col * BSW + kw0 + 4];
        }

        #pragma unroll
        for (int mt = 0; mt < 2; mt++)
            #pragma unroll
            for (int nt = 0; nt < 4; nt++)
                mma_bf16(d[mt * 4 + nt], a[mt], b[nt]);
    }

    // ---- wait own weights; warp-local from here on ----
    CP_WAIT(0);
    __syncwarp();

    float* tb = (float*)(smem + OFF_TB) + wid * 8 * TBS;
    const float* w_sm = (const float*)(smem + OFF_WT) + wid * 1024;
    float* oseg = out + (size_t)row_g * 2048 + colbase;

    // ---- 4 passes x 8 j-rows: transpose frag -> tb -> coalesced add+store ----
    // fragment: d[half*4+nt] holds j-rows (half*16+g, half*16+g+8), cols nt*8+2tig
    #pragma unroll
    for (int half = 0; half < 2; half++) {
        #pragma unroll
        for (int sub = 0; sub < 2; sub++) {          // sub=0: rows g; sub=1: rows g+8
            #pragma unroll
            for (int nt = 0; nt < 4; nt++) {
                const int bb = nt * 8 + 2 * tig;
                const float* dd = d[half * 4 + nt];
                *(float2*)&tb[g * TBS + bb] = make_float2(dd[sub * 2], dd[sub * 2 + 1]);
            }
            __syncwarp();

            const int jbase = half * 16 + sub * 8;
            #pragma unroll
            for (int it = 0; it < 2; it++) {
                const int jl = it * 4 + (lane >> 3);     // 0..7
                const int c4 = (lane & 7) * 4;
                const int col = (jbase + jl) * 32 + c4;

                const float4 dv = *(const float4*)&tb[jl * TBS + c4];
                const float4 wv = *(const float4*)&w_sm[col];
                float4 ov;
                ov.x = wv.x + dv.x;
                ov.y = wv.y + dv.y;
                ov.z = wv.z + dv.z;
                ov.w = wv.w + dv.w;
                *(float4*)(oseg + col) = ov;
            }
            __syncwarp();
        }
    }
}

extern "C" void kernel_launch(void* const* d_in, const int* in_sizes, int n_in,
                              void* d_out, int out_size)
{
    const float* weights = (const float*)d_in[0];
    const float* pos     = (const float*)d_in[1];
    const float* pw      = (const float*)d_in[2];
    const float* ph      = (const float*)d_in[3];
    float* out           = (float*)d_out;

    splopa_prep_kernel<<<160, 256>>>(pos, pw, ph);
    dim3 grid(16, 32);
    splopa_mma_kernel<<<grid, dim3(256)>>>(weights, out);
}